// round 10
// baseline (speedup 1.0000x reference)
#include <cuda_runtime.h>
#include <cuda_bf16.h>
#include <cstdint>

// ---------------------------------------------------------------------------
// GraphSAGE 2-layer backbone, CSR gather-reduce + FFMA2 dense (R8 structure).
// R10: weights __ldg'd as ulonglong2 -> FFMA2 weight operands come straight
//      from LDG.128 halves (no pk2 movs). Everything else identical to R8.
// ---------------------------------------------------------------------------

static constexpr int NN   = 100000;
static constexpr int EE   = 1600000;
static constexpr int F_IN = 64;
static constexpr int F_H  = 128;
static constexpr int SCAN_CHUNK = 512;

__device__ __align__(16) float g_agg1 [(size_t)NN * F_IN];
__device__ __align__(16) float g_h    [(size_t)NN * F_H];
__device__ __align__(16) float g_agg2 [(size_t)NN * F_H];
__device__ __align__(16) float g_dinv [NN];
__device__ __align__(16) int   g_degi [NN];      // zero at load; final re-zeroes
__device__ __align__(16) int   g_rowp [NN + 1];
__device__ __align__(16) int   g_curs [NN];
__device__ __align__(16) int   g_csr  [EE];
__device__ __align__(16) int   g_bsum [256];
__device__ __align__(16) int   g_boff [256];
__device__ __align__(16) float g_w1t  [2 * F_IN * 128];
__device__ __align__(16) float g_w2t  [2 * F_H  * 128];

// ---------------------------------------------------------------------------
__device__ __forceinline__ unsigned long long pk2(float a, float b) {
    unsigned long long r;
    asm("mov.b64 %0, {%1, %2};" : "=l"(r) : "f"(a), "f"(b));
    return r;
}
__device__ __forceinline__ void fma2(unsigned long long& d,
                                     unsigned long long a,
                                     unsigned long long b) {
    asm("fma.rn.f32x2 %0, %1, %2, %0;" : "+l"(d) : "l"(a), "l"(b));
}
__device__ __forceinline__ float2 upk2(unsigned long long v) {
    float2 f;
    asm("mov.b64 {%0, %1}, %2;" : "=f"(f.x), "=f"(f.y) : "l"(v));
    return f;
}

// ---------------------------------------------------------------------------
__global__ void pack_all_kernel(const float* __restrict__ W1l,
                                const float* __restrict__ W1r,
                                const float* __restrict__ W2l,
                                const float* __restrict__ W2r,
                                float* __restrict__ w1t,
                                float* __restrict__ w2t) {
    int i = blockIdx.x * blockDim.x + threadIdx.x;
    if (i < 2 * F_IN * 128) {
        int k = i >> 7, j = i & 127;
        w1t[i] = (k < F_IN) ? W1l[j * F_IN + k] : W1r[j * F_IN + (k - F_IN)];
    }
    if (i < 2 * F_H * 128) {
        int k = i >> 7, j = i & 127;
        w2t[i] = (k < F_H) ? W2l[j * F_H + k] : W2r[j * F_H + (k - F_H)];
    }
}

__global__ void hist_kernel(const int* __restrict__ ei, int E, int nnodes,
                            int* __restrict__ degi) {
    int e = blockIdx.x * blockDim.x + threadIdx.x;
    if (e >= E) return;
    int dst = __ldg(&ei[E + e]);
    if ((unsigned)dst < (unsigned)nnodes) atomicAdd(&degi[dst], 1);
}

// ---- coalesced 3-pass exclusive scan over degi ----
__global__ void scan_partial_kernel(const int* __restrict__ degi,
                                    int* __restrict__ bsum, int n) {
    __shared__ int s[SCAN_CHUNK];
    int t = threadIdx.x;
    int i = blockIdx.x * SCAN_CHUNK + t;
    s[t] = (i < n) ? degi[i] : 0;
    __syncthreads();
    for (int off = SCAN_CHUNK / 2; off > 0; off >>= 1) {
        if (t < off) s[t] += s[t + off];
        __syncthreads();
    }
    if (t == 0) bsum[blockIdx.x] = s[0];
}

__global__ void scan_bsum_kernel(const int* __restrict__ bsum,
                                 int* __restrict__ boff,
                                 int* __restrict__ rowp,
                                 int nblk, int n) {
    __shared__ int s[256];
    int t = threadIdx.x;
    s[t] = (t < nblk) ? bsum[t] : 0;
    __syncthreads();
    for (int off = 1; off < 256; off <<= 1) {
        int v = (t >= off) ? s[t - off] : 0;
        __syncthreads();
        s[t] += v;
        __syncthreads();
    }
    boff[t] = (t == 0) ? 0 : s[t - 1];
    if (t == 255) rowp[n] = s[255];
}

__global__ void scan_final_kernel(int* __restrict__ degi,
                                  const int* __restrict__ boff,
                                  int* __restrict__ rowp,
                                  int* __restrict__ curs,
                                  float* __restrict__ dinv, int n) {
    __shared__ int s[SCAN_CHUNK];
    int t = threadIdx.x;
    int i = blockIdx.x * SCAN_CHUNK + t;
    int d = (i < n) ? degi[i] : 0;
    s[t] = d;
    __syncthreads();
    for (int off = 1; off < SCAN_CHUNK; off <<= 1) {
        int v = (t >= off) ? s[t - off] : 0;
        __syncthreads();
        s[t] += v;
        __syncthreads();
    }
    if (i < n) {
        int excl = s[t] - d + boff[blockIdx.x];
        rowp[i] = excl;
        curs[i] = excl;
        dinv[i] = 1.0f / fmaxf((float)d, 1.0f);
        degi[i] = 0;
    }
}

__global__ void scatter_kernel(const int* __restrict__ ei, int E, int nnodes,
                               int* __restrict__ curs,
                               int* __restrict__ csr) {
    int e = blockIdx.x * blockDim.x + threadIdx.x;
    if (e >= E) return;
    int src = __ldg(&ei[e]);
    int dst = __ldg(&ei[E + e]);
    if ((unsigned)src >= (unsigned)nnodes || (unsigned)dst >= (unsigned)nnodes) return;
    int pos = atomicAdd(&curs[dst], 1);
    csr[pos] = src;
}

// Gather-reduce mean aggregation, 4-way unroll.
template <int F4>
__global__ void gather_agg_kernel(const float4* __restrict__ in4,
                                  const int* __restrict__ rowp,
                                  const int* __restrict__ csr,
                                  const float* __restrict__ dinv,
                                  float4* __restrict__ aggout,
                                  int n) {
    constexpr int GPB = 256 / F4;
    const int node = blockIdx.x * GPB + (threadIdx.x / F4);
    const int lane = threadIdx.x & (F4 - 1);
    if (node >= n) return;

    const int beg = __ldg(&rowp[node]);
    const int end = __ldg(&rowp[node + 1]);

    float4 a0 = make_float4(0.f, 0.f, 0.f, 0.f);
    float4 a1 = make_float4(0.f, 0.f, 0.f, 0.f);
    float4 a2 = make_float4(0.f, 0.f, 0.f, 0.f);
    float4 a3 = make_float4(0.f, 0.f, 0.f, 0.f);

    int j = beg;
    for (; j + 4 <= end; j += 4) {
        int s0 = __ldg(&csr[j]);
        int s1 = __ldg(&csr[j + 1]);
        int s2 = __ldg(&csr[j + 2]);
        int s3 = __ldg(&csr[j + 3]);
        float4 v0 = __ldg(&in4[(size_t)s0 * F4 + lane]);
        float4 v1 = __ldg(&in4[(size_t)s1 * F4 + lane]);
        float4 v2 = __ldg(&in4[(size_t)s2 * F4 + lane]);
        float4 v3 = __ldg(&in4[(size_t)s3 * F4 + lane]);
        a0.x += v0.x; a0.y += v0.y; a0.z += v0.z; a0.w += v0.w;
        a1.x += v1.x; a1.y += v1.y; a1.z += v1.z; a1.w += v1.w;
        a2.x += v2.x; a2.y += v2.y; a2.z += v2.z; a2.w += v2.w;
        a3.x += v3.x; a3.y += v3.y; a3.z += v3.z; a3.w += v3.w;
    }
    for (; j < end; j++) {
        int s0 = __ldg(&csr[j]);
        float4 v0 = __ldg(&in4[(size_t)s0 * F4 + lane]);
        a0.x += v0.x; a0.y += v0.y; a0.z += v0.z; a0.w += v0.w;
    }

    const float di = __ldg(&dinv[node]);
    float4 r;
    r.x = (a0.x + a1.x + a2.x + a3.x) * di;
    r.y = (a0.y + a1.y + a2.y + a3.y) * di;
    r.z = (a0.z + a1.z + a2.z + a3.z) * di;
    r.w = (a0.w + a1.w + a2.w + a3.w) * di;
    aggout[(size_t)node * F4 + lane] = r;
}

// Fused dense layer (R8 structure), f32x2 accumulators.
// Weights __ldg'd as ulonglong2 -> native 64-bit operand pairs, no packing movs.
// Activation tile (64 nodes * K2) in smem; bias in smem.
template <int K, bool RELU>
__global__ void __launch_bounds__(256)
dense_kernel(const float* __restrict__ xin,
             const float* __restrict__ agg,
             const float* __restrict__ WcT,
             const float* __restrict__ bias,
             float* __restrict__ out,
             int nnodes) {
    constexpr int K2 = 2 * K;
    extern __shared__ float sm[];
    float* sC = sm;                 // 64 nodes * K2, layout [n][k]
    __shared__ float sB[128];

    const int tid  = threadIdx.x;
    const int base = blockIdx.x * 64;

    if (tid < 128) sB[tid] = bias[tid];
    {
        constexpr int KQ = K / 4;
        const float4* x4 = reinterpret_cast<const float4*>(xin);
        const float4* a4 = reinterpret_cast<const float4*>(agg);
        float4 z = make_float4(0.f, 0.f, 0.f, 0.f);
        for (int i = tid; i < 64 * KQ; i += 256) {
            int n  = i / KQ;
            int kq = i - n * KQ;
            int node = base + n;
            float4 xv = z, av = z;
            if (node < nnodes) {
                size_t off = (size_t)node * KQ + kq;
                xv = x4[off];
                av = a4[off];
            }
            reinterpret_cast<float4*>(sC + n * K2)[kq]     = av;
            reinterpret_cast<float4*>(sC + n * K2 + K)[kq] = xv;
        }
    }
    __syncthreads();

    const int w = tid >> 5;
    const int l = tid & 31;

    unsigned long long acc01[8], acc23[8];
    {
        unsigned long long b01 = pk2(sB[4 * l], sB[4 * l + 1]);
        unsigned long long b23 = pk2(sB[4 * l + 2], sB[4 * l + 3]);
#pragma unroll
        for (int m = 0; m < 8; m++) { acc01[m] = b01; acc23[m] = b23; }
    }

    const ulonglong2* W16 = reinterpret_cast<const ulonglong2*>(WcT);
    const float4*     sC4 = reinterpret_cast<const float4*>(sC + (w * 8) * K2);

#pragma unroll 2
    for (int k4 = 0; k4 < K2 / 4; k4++) {
        // L1-hot LDG.128s; halves are native 64-bit register pairs
        ulonglong2 w0 = __ldg(&W16[(4 * k4 + 0) * 32 + l]);
        ulonglong2 w1 = __ldg(&W16[(4 * k4 + 1) * 32 + l]);
        ulonglong2 w2 = __ldg(&W16[(4 * k4 + 2) * 32 + l]);
        ulonglong2 w3 = __ldg(&W16[(4 * k4 + 3) * 32 + l]);
#pragma unroll
        for (int m = 0; m < 8; m++) {
            float4 c4 = sC4[m * (K2 / 4) + k4];                // broadcast LDS.128
            unsigned long long cc;
            cc = pk2(c4.x, c4.x); fma2(acc01[m], cc, w0.x); fma2(acc23[m], cc, w0.y);
            cc = pk2(c4.y, c4.y); fma2(acc01[m], cc, w1.x); fma2(acc23[m], cc, w1.y);
            cc = pk2(c4.z, c4.z); fma2(acc01[m], cc, w2.x); fma2(acc23[m], cc, w2.y);
            cc = pk2(c4.w, c4.w); fma2(acc01[m], cc, w3.x); fma2(acc23[m], cc, w3.y);
        }
    }

#pragma unroll
    for (int m = 0; m < 8; m++) {
        int node = base + w * 8 + m;
        if (node >= nnodes) continue;
        float2 p01 = upk2(acc01[m]);
        float2 p23 = upk2(acc23[m]);
        float4 o;
        o.x = p01.x; o.y = p01.y; o.z = p23.x; o.w = p23.y;
        if (RELU) {
            o.x = fmaxf(o.x, 0.f); o.y = fmaxf(o.y, 0.f);
            o.z = fmaxf(o.z, 0.f); o.w = fmaxf(o.w, 0.f);
        }
        reinterpret_cast<float4*>(out)[(size_t)node * 32 + l] = o;
    }
}

// ---------------------------------------------------------------------------
extern "C" void kernel_launch(void* const* d_in, const int* in_sizes, int n_in,
                              void* d_out, int out_size) {
    const float* x    = (const float*)d_in[0];
    const int*   ei   = (const int*)d_in[1];
    const float* W1_l = (const float*)d_in[2];
    const float* b1   = (const float*)d_in[3];
    const float* W1_r = (const float*)d_in[4];
    const float* W2_l = (const float*)d_in[5];
    const float* b2   = (const float*)d_in[6];
    const float* W2_r = (const float*)d_in[7];
    float*       out  = (float*)d_out;

    const int n = in_sizes[0] / F_IN;   // 100000
    const int E = in_sizes[1] / 2;      // 1600000
    const int nblk = (n + SCAN_CHUNK - 1) / SCAN_CHUNK;

    void *p_agg1, *p_h, *p_agg2, *p_dinv, *p_degi, *p_rowp, *p_curs, *p_csr,
         *p_bsum, *p_boff, *p_w1t, *p_w2t;
    cudaGetSymbolAddress(&p_agg1, g_agg1);
    cudaGetSymbolAddress(&p_h,    g_h);
    cudaGetSymbolAddress(&p_agg2, g_agg2);
    cudaGetSymbolAddress(&p_dinv, g_dinv);
    cudaGetSymbolAddress(&p_degi, g_degi);
    cudaGetSymbolAddress(&p_rowp, g_rowp);
    cudaGetSymbolAddress(&p_curs, g_curs);
    cudaGetSymbolAddress(&p_csr,  g_csr);
    cudaGetSymbolAddress(&p_bsum, g_bsum);
    cudaGetSymbolAddress(&p_boff, g_boff);
    cudaGetSymbolAddress(&p_w1t,  g_w1t);
    cudaGetSymbolAddress(&p_w2t,  g_w2t);
    float* agg1 = (float*)p_agg1;
    float* h    = (float*)p_h;
    float* agg2 = (float*)p_agg2;
    float* dinv = (float*)p_dinv;
    int*   degi = (int*)p_degi;
    int*   rowp = (int*)p_rowp;
    int*   curs = (int*)p_curs;
    int*   csr  = (int*)p_csr;
    int*   bsum = (int*)p_bsum;
    int*   boff = (int*)p_boff;
    float* w1t  = (float*)p_w1t;
    float* w2t  = (float*)p_w2t;

    const int smem1 = 64 * 2 * F_IN * (int)sizeof(float); // 32KB
    const int smem2 = 64 * 2 * F_H  * (int)sizeof(float); // 64KB
    cudaFuncSetAttribute(dense_kernel<F_IN, true>,
                         cudaFuncAttributeMaxDynamicSharedMemorySize, smem1);
    cudaFuncSetAttribute(dense_kernel<F_H, false>,
                         cudaFuncAttributeMaxDynamicSharedMemorySize, smem2);

    // CSR build (degi zero: zero-init at load, re-zeroed by scan_final)
    hist_kernel<<<(E + 255) / 256, 256>>>(ei, E, n, degi);
    scan_partial_kernel<<<nblk, SCAN_CHUNK>>>(degi, bsum, n);
    scan_bsum_kernel<<<1, 256>>>(bsum, boff, rowp, nblk, n);
    scan_final_kernel<<<nblk, SCAN_CHUNK>>>(degi, boff, rowp, curs, dinv, n);
    scatter_kernel<<<(E + 255) / 256, 256>>>(ei, E, n, curs, csr);

    // layer 1
    gather_agg_kernel<F_IN / 4><<<(n * (F_IN / 4) + 255) / 256, 256>>>(
        (const float4*)x, rowp, csr, dinv, (float4*)agg1, n);
    pack_all_kernel<<<(2 * F_H * 128 + 255) / 256, 256>>>(
        W1_l, W1_r, W2_l, W2_r, w1t, w2t);
    dense_kernel<F_IN, true><<<(n + 63) / 64, 256, smem1>>>(
        x, agg1, w1t, b1, h, n);

    // layer 2
    gather_agg_kernel<F_H / 4><<<(n * (F_H / 4) + 255) / 256, 256>>>(
        (const float4*)h, rowp, csr, dinv, (float4*)agg2, n);
    dense_kernel<F_H, false><<<(n + 63) / 64, 256, smem2>>>(
        h, agg2, w2t, b2, out, n);
}

// round 11
// speedup vs baseline: 1.4741x; 1.4741x over previous
#include <cuda_runtime.h>
#include <cuda_bf16.h>
#include <cstdint>

// ---------------------------------------------------------------------------
// GraphSAGE 2-layer backbone, CSR gather-reduce + FFMA2 dense.
// R11: dense reverted to exact R8 form (best known: 384us).
//      hist/scatter vectorized: 2 edges per thread via int2 loads.
// ---------------------------------------------------------------------------

static constexpr int NN   = 100000;
static constexpr int EE   = 1600000;
static constexpr int F_IN = 64;
static constexpr int F_H  = 128;
static constexpr int SCAN_CHUNK = 512;

__device__ __align__(16) float g_agg1 [(size_t)NN * F_IN];
__device__ __align__(16) float g_h    [(size_t)NN * F_H];
__device__ __align__(16) float g_agg2 [(size_t)NN * F_H];
__device__ __align__(16) float g_dinv [NN];
__device__ __align__(16) int   g_degi [NN];      // zero at load; final re-zeroes
__device__ __align__(16) int   g_rowp [NN + 1];
__device__ __align__(16) int   g_curs [NN];
__device__ __align__(16) int   g_csr  [EE];
__device__ __align__(16) int   g_bsum [256];
__device__ __align__(16) int   g_boff [256];
__device__ __align__(16) float g_w1t  [2 * F_IN * 128];
__device__ __align__(16) float g_w2t  [2 * F_H  * 128];

// ---------------------------------------------------------------------------
__device__ __forceinline__ unsigned long long pk2(float a, float b) {
    unsigned long long r;
    asm("mov.b64 %0, {%1, %2};" : "=l"(r) : "f"(a), "f"(b));
    return r;
}
__device__ __forceinline__ void fma2(unsigned long long& d,
                                     unsigned long long a,
                                     unsigned long long b) {
    asm("fma.rn.f32x2 %0, %1, %2, %0;" : "+l"(d) : "l"(a), "l"(b));
}
__device__ __forceinline__ float2 upk2(unsigned long long v) {
    float2 f;
    asm("mov.b64 {%0, %1}, %2;" : "=f"(f.x), "=f"(f.y) : "l"(v));
    return f;
}

// ---------------------------------------------------------------------------
__global__ void pack_all_kernel(const float* __restrict__ W1l,
                                const float* __restrict__ W1r,
                                const float* __restrict__ W2l,
                                const float* __restrict__ W2r,
                                float* __restrict__ w1t,
                                float* __restrict__ w2t) {
    int i = blockIdx.x * blockDim.x + threadIdx.x;
    if (i < 2 * F_IN * 128) {
        int k = i >> 7, j = i & 127;
        w1t[i] = (k < F_IN) ? W1l[j * F_IN + k] : W1r[j * F_IN + (k - F_IN)];
    }
    if (i < 2 * F_H * 128) {
        int k = i >> 7, j = i & 127;
        w2t[i] = (k < F_H) ? W2l[j * F_H + k] : W2r[j * F_H + (k - F_H)];
    }
}

// Histogram of dst, 2 edges per thread (E assumed even; tail guarded).
__global__ void hist_kernel(const int* __restrict__ ei, int E, int nnodes,
                            int* __restrict__ degi) {
    const int half = E >> 1;
    int i = blockIdx.x * blockDim.x + threadIdx.x;
    if (i < half) {
        int2 d2 = __ldg(reinterpret_cast<const int2*>(ei + E) + i);
        if ((unsigned)d2.x < (unsigned)nnodes) atomicAdd(&degi[d2.x], 1);
        if ((unsigned)d2.y < (unsigned)nnodes) atomicAdd(&degi[d2.y], 1);
    }
    if ((E & 1) && i == 0) {
        int d = __ldg(&ei[E + E - 1]);
        if ((unsigned)d < (unsigned)nnodes) atomicAdd(&degi[d], 1);
    }
}

// ---- coalesced 3-pass exclusive scan over degi ----
__global__ void scan_partial_kernel(const int* __restrict__ degi,
                                    int* __restrict__ bsum, int n) {
    __shared__ int s[SCAN_CHUNK];
    int t = threadIdx.x;
    int i = blockIdx.x * SCAN_CHUNK + t;
    s[t] = (i < n) ? degi[i] : 0;
    __syncthreads();
    for (int off = SCAN_CHUNK / 2; off > 0; off >>= 1) {
        if (t < off) s[t] += s[t + off];
        __syncthreads();
    }
    if (t == 0) bsum[blockIdx.x] = s[0];
}

__global__ void scan_bsum_kernel(const int* __restrict__ bsum,
                                 int* __restrict__ boff,
                                 int* __restrict__ rowp,
                                 int nblk, int n) {
    __shared__ int s[256];
    int t = threadIdx.x;
    s[t] = (t < nblk) ? bsum[t] : 0;
    __syncthreads();
    for (int off = 1; off < 256; off <<= 1) {
        int v = (t >= off) ? s[t - off] : 0;
        __syncthreads();
        s[t] += v;
        __syncthreads();
    }
    boff[t] = (t == 0) ? 0 : s[t - 1];
    if (t == 255) rowp[n] = s[255];
}

__global__ void scan_final_kernel(int* __restrict__ degi,
                                  const int* __restrict__ boff,
                                  int* __restrict__ rowp,
                                  int* __restrict__ curs,
                                  float* __restrict__ dinv, int n) {
    __shared__ int s[SCAN_CHUNK];
    int t = threadIdx.x;
    int i = blockIdx.x * SCAN_CHUNK + t;
    int d = (i < n) ? degi[i] : 0;
    s[t] = d;
    __syncthreads();
    for (int off = 1; off < SCAN_CHUNK; off <<= 1) {
        int v = (t >= off) ? s[t - off] : 0;
        __syncthreads();
        s[t] += v;
        __syncthreads();
    }
    if (i < n) {
        int excl = s[t] - d + boff[blockIdx.x];
        rowp[i] = excl;
        curs[i] = excl;
        dinv[i] = 1.0f / fmaxf((float)d, 1.0f);
        degi[i] = 0;
    }
}

// Counting-sort scatter, 2 edges per thread.
__global__ void scatter_kernel(const int* __restrict__ ei, int E, int nnodes,
                               int* __restrict__ curs,
                               int* __restrict__ csr) {
    const int half = E >> 1;
    int i = blockIdx.x * blockDim.x + threadIdx.x;
    if (i < half) {
        int2 s2 = __ldg(reinterpret_cast<const int2*>(ei) + i);
        int2 d2 = __ldg(reinterpret_cast<const int2*>(ei + E) + i);
        if ((unsigned)s2.x < (unsigned)nnodes && (unsigned)d2.x < (unsigned)nnodes) {
            int pos = atomicAdd(&curs[d2.x], 1);
            csr[pos] = s2.x;
        }
        if ((unsigned)s2.y < (unsigned)nnodes && (unsigned)d2.y < (unsigned)nnodes) {
            int pos = atomicAdd(&curs[d2.y], 1);
            csr[pos] = s2.y;
        }
    }
    if ((E & 1) && i == 0) {
        int s = __ldg(&ei[E - 1]);
        int d = __ldg(&ei[E + E - 1]);
        if ((unsigned)s < (unsigned)nnodes && (unsigned)d < (unsigned)nnodes) {
            int pos = atomicAdd(&curs[d], 1);
            csr[pos] = s;
        }
    }
}

// Gather-reduce mean aggregation, 4-way unroll.
template <int F4>
__global__ void gather_agg_kernel(const float4* __restrict__ in4,
                                  const int* __restrict__ rowp,
                                  const int* __restrict__ csr,
                                  const float* __restrict__ dinv,
                                  float4* __restrict__ aggout,
                                  int n) {
    constexpr int GPB = 256 / F4;
    const int node = blockIdx.x * GPB + (threadIdx.x / F4);
    const int lane = threadIdx.x & (F4 - 1);
    if (node >= n) return;

    const int beg = __ldg(&rowp[node]);
    const int end = __ldg(&rowp[node + 1]);

    float4 a0 = make_float4(0.f, 0.f, 0.f, 0.f);
    float4 a1 = make_float4(0.f, 0.f, 0.f, 0.f);
    float4 a2 = make_float4(0.f, 0.f, 0.f, 0.f);
    float4 a3 = make_float4(0.f, 0.f, 0.f, 0.f);

    int j = beg;
    for (; j + 4 <= end; j += 4) {
        int s0 = __ldg(&csr[j]);
        int s1 = __ldg(&csr[j + 1]);
        int s2 = __ldg(&csr[j + 2]);
        int s3 = __ldg(&csr[j + 3]);
        float4 v0 = __ldg(&in4[(size_t)s0 * F4 + lane]);
        float4 v1 = __ldg(&in4[(size_t)s1 * F4 + lane]);
        float4 v2 = __ldg(&in4[(size_t)s2 * F4 + lane]);
        float4 v3 = __ldg(&in4[(size_t)s3 * F4 + lane]);
        a0.x += v0.x; a0.y += v0.y; a0.z += v0.z; a0.w += v0.w;
        a1.x += v1.x; a1.y += v1.y; a1.z += v1.z; a1.w += v1.w;
        a2.x += v2.x; a2.y += v2.y; a2.z += v2.z; a2.w += v2.w;
        a3.x += v3.x; a3.y += v3.y; a3.z += v3.z; a3.w += v3.w;
    }
    for (; j < end; j++) {
        int s0 = __ldg(&csr[j]);
        float4 v0 = __ldg(&in4[(size_t)s0 * F4 + lane]);
        a0.x += v0.x; a0.y += v0.y; a0.z += v0.z; a0.w += v0.w;
    }

    const float di = __ldg(&dinv[node]);
    float4 r;
    r.x = (a0.x + a1.x + a2.x + a3.x) * di;
    r.y = (a0.y + a1.y + a2.y + a3.y) * di;
    r.z = (a0.z + a1.z + a2.z + a3.z) * di;
    r.w = (a0.w + a1.w + a2.w + a3.w) * di;
    aggout[(size_t)node * F4 + lane] = r;
}

// Fused dense layer — EXACT R8 structure (best measured: 384us total).
// f32x2 accumulators; weights __ldg'd as float4 + pk2; activation tile in smem.
template <int K, bool RELU>
__global__ void __launch_bounds__(256)
dense_kernel(const float* __restrict__ xin,
             const float* __restrict__ agg,
             const float* __restrict__ WcT,
             const float* __restrict__ bias,
             float* __restrict__ out,
             int nnodes) {
    constexpr int K2 = 2 * K;
    extern __shared__ float sm[];
    float* sC = sm;                 // 64 nodes * K2, layout [n][k]
    __shared__ float sB[128];

    const int tid  = threadIdx.x;
    const int base = blockIdx.x * 64;

    if (tid < 128) sB[tid] = bias[tid];
    {
        constexpr int KQ = K / 4;
        const float4* x4 = reinterpret_cast<const float4*>(xin);
        const float4* a4 = reinterpret_cast<const float4*>(agg);
        float4 z = make_float4(0.f, 0.f, 0.f, 0.f);
        for (int i = tid; i < 64 * KQ; i += 256) {
            int n  = i / KQ;
            int kq = i - n * KQ;
            int node = base + n;
            float4 xv = z, av = z;
            if (node < nnodes) {
                size_t off = (size_t)node * KQ + kq;
                xv = x4[off];
                av = a4[off];
            }
            reinterpret_cast<float4*>(sC + n * K2)[kq]     = av;
            reinterpret_cast<float4*>(sC + n * K2 + K)[kq] = xv;
        }
    }
    __syncthreads();

    const int w = tid >> 5;
    const int l = tid & 31;

    unsigned long long acc01[8], acc23[8];
    {
        unsigned long long b01 = pk2(sB[4 * l], sB[4 * l + 1]);
        unsigned long long b23 = pk2(sB[4 * l + 2], sB[4 * l + 3]);
#pragma unroll
        for (int m = 0; m < 8; m++) { acc01[m] = b01; acc23[m] = b23; }
    }

    const float4* W4  = reinterpret_cast<const float4*>(WcT);
    const float4* sC4 = reinterpret_cast<const float4*>(sC + (w * 8) * K2);

#pragma unroll 2
    for (int k4 = 0; k4 < K2 / 4; k4++) {
        unsigned long long wp[4][2];
#pragma unroll
        for (int kk = 0; kk < 4; kk++) {
            float4 wv = __ldg(&W4[(4 * k4 + kk) * 32 + l]);   // L1-hot LDG.128
            wp[kk][0] = pk2(wv.x, wv.y);
            wp[kk][1] = pk2(wv.z, wv.w);
        }
#pragma unroll
        for (int m = 0; m < 8; m++) {
            float4 c4 = sC4[m * (K2 / 4) + k4];                // broadcast LDS.128
            unsigned long long cc;
            cc = pk2(c4.x, c4.x); fma2(acc01[m], cc, wp[0][0]); fma2(acc23[m], cc, wp[0][1]);
            cc = pk2(c4.y, c4.y); fma2(acc01[m], cc, wp[1][0]); fma2(acc23[m], cc, wp[1][1]);
            cc = pk2(c4.z, c4.z); fma2(acc01[m], cc, wp[2][0]); fma2(acc23[m], cc, wp[2][1]);
            cc = pk2(c4.w, c4.w); fma2(acc01[m], cc, wp[3][0]); fma2(acc23[m], cc, wp[3][1]);
        }
    }

#pragma unroll
    for (int m = 0; m < 8; m++) {
        int node = base + w * 8 + m;
        if (node >= nnodes) continue;
        float2 p01 = upk2(acc01[m]);
        float2 p23 = upk2(acc23[m]);
        float4 o;
        o.x = p01.x; o.y = p01.y; o.z = p23.x; o.w = p23.y;
        if (RELU) {
            o.x = fmaxf(o.x, 0.f); o.y = fmaxf(o.y, 0.f);
            o.z = fmaxf(o.z, 0.f); o.w = fmaxf(o.w, 0.f);
        }
        reinterpret_cast<float4*>(out)[(size_t)node * 32 + l] = o;
    }
}

// ---------------------------------------------------------------------------
extern "C" void kernel_launch(void* const* d_in, const int* in_sizes, int n_in,
                              void* d_out, int out_size) {
    const float* x    = (const float*)d_in[0];
    const int*   ei   = (const int*)d_in[1];
    const float* W1_l = (const float*)d_in[2];
    const float* b1   = (const float*)d_in[3];
    const float* W1_r = (const float*)d_in[4];
    const float* W2_l = (const float*)d_in[5];
    const float* b2   = (const float*)d_in[6];
    const float* W2_r = (const float*)d_in[7];
    float*       out  = (float*)d_out;

    const int n = in_sizes[0] / F_IN;   // 100000
    const int E = in_sizes[1] / 2;      // 1600000
    const int nblk = (n + SCAN_CHUNK - 1) / SCAN_CHUNK;

    void *p_agg1, *p_h, *p_agg2, *p_dinv, *p_degi, *p_rowp, *p_curs, *p_csr,
         *p_bsum, *p_boff, *p_w1t, *p_w2t;
    cudaGetSymbolAddress(&p_agg1, g_agg1);
    cudaGetSymbolAddress(&p_h,    g_h);
    cudaGetSymbolAddress(&p_agg2, g_agg2);
    cudaGetSymbolAddress(&p_dinv, g_dinv);
    cudaGetSymbolAddress(&p_degi, g_degi);
    cudaGetSymbolAddress(&p_rowp, g_rowp);
    cudaGetSymbolAddress(&p_curs, g_curs);
    cudaGetSymbolAddress(&p_csr,  g_csr);
    cudaGetSymbolAddress(&p_bsum, g_bsum);
    cudaGetSymbolAddress(&p_boff, g_boff);
    cudaGetSymbolAddress(&p_w1t,  g_w1t);
    cudaGetSymbolAddress(&p_w2t,  g_w2t);
    float* agg1 = (float*)p_agg1;
    float* h    = (float*)p_h;
    float* agg2 = (float*)p_agg2;
    float* dinv = (float*)p_dinv;
    int*   degi = (int*)p_degi;
    int*   rowp = (int*)p_rowp;
    int*   curs = (int*)p_curs;
    int*   csr  = (int*)p_csr;
    int*   bsum = (int*)p_bsum;
    int*   boff = (int*)p_boff;
    float* w1t  = (float*)p_w1t;
    float* w2t  = (float*)p_w2t;

    const int smem1 = 64 * 2 * F_IN * (int)sizeof(float); // 32KB
    const int smem2 = 64 * 2 * F_H  * (int)sizeof(float); // 64KB
    cudaFuncSetAttribute(dense_kernel<F_IN, true>,
                         cudaFuncAttributeMaxDynamicSharedMemorySize, smem1);
    cudaFuncSetAttribute(dense_kernel<F_H, false>,
                         cudaFuncAttributeMaxDynamicSharedMemorySize, smem2);

    // CSR build (degi zero: zero-init at load, re-zeroed by scan_final)
    hist_kernel<<<((E >> 1) + 255) / 256, 256>>>(ei, E, n, degi);
    scan_partial_kernel<<<nblk, SCAN_CHUNK>>>(degi, bsum, n);
    scan_bsum_kernel<<<1, 256>>>(bsum, boff, rowp, nblk, n);
    scan_final_kernel<<<nblk, SCAN_CHUNK>>>(degi, boff, rowp, curs, dinv, n);
    scatter_kernel<<<((E >> 1) + 255) / 256, 256>>>(ei, E, n, curs, csr);

    // layer 1
    gather_agg_kernel<F_IN / 4><<<(n * (F_IN / 4) + 255) / 256, 256>>>(
        (const float4*)x, rowp, csr, dinv, (float4*)agg1, n);
    pack_all_kernel<<<(2 * F_H * 128 + 255) / 256, 256>>>(
        W1_l, W1_r, W2_l, W2_r, w1t, w2t);
    dense_kernel<F_IN, true><<<(n + 63) / 64, 256, smem1>>>(
        x, agg1, w1t, b1, h, n);

    // layer 2
    gather_agg_kernel<F_H / 4><<<(n * (F_H / 4) + 255) / 256, 256>>>(
        (const float4*)h, rowp, csr, dinv, (float4*)agg2, n);
    dense_kernel<F_H, false><<<(n + 63) / 64, 256, smem2>>>(
        h, agg2, w2t, b2, out, n);
}

// round 13
// speedup vs baseline: 1.8724x; 1.2702x over previous
#include <cuda_runtime.h>
#include <cuda_bf16.h>
#include <cstdint>

// ---------------------------------------------------------------------------
// GraphSAGE 2-layer backbone.
// R13: dense layers on warp-level mma.sync bf16 (baseline PTX, sm_80+ —
//      tcgen05 is unavailable: harness compiles .target sm_103 without 'a').
//      bf16 hi/lo split, 3 products (hi*hi + hi*lo + lo*hi), fp32 accum.
// CSR gather-reduce aggregation unchanged (R11).
// ---------------------------------------------------------------------------

static constexpr int NN   = 100000;
static constexpr int EE   = 1600000;
static constexpr int F_IN = 64;
static constexpr int F_H  = 128;
static constexpr int SCAN_CHUNK = 512;

// A-tile smem: 128 rows, 64 k bf16 per chunk, row stride 144B (16B aligned,
// 36 words -> ldmatrix rows land on distinct bank groups).
static constexpr int A_STRIDE = 144;
static constexpr int A_TILE   = 128 * A_STRIDE;          // 18432 B per split
static constexpr int SMEM_BIAS_OFF = 2 * A_TILE;          // 36864
static constexpr int SMEM_TOTAL_D  = SMEM_BIAS_OFF + 512; // 37376

// scratch
__device__ __align__(16) float g_agg1 [(size_t)NN * F_IN];
__device__ __align__(16) float g_h    [(size_t)NN * F_H];
__device__ __align__(16) float g_agg2 [(size_t)NN * F_H];
__device__ __align__(16) float g_dinv [NN];
__device__ __align__(16) int   g_degi [NN];
__device__ __align__(16) int   g_rowp [NN + 1];
__device__ __align__(16) int   g_curs [NN];
__device__ __align__(16) int   g_csr  [EE];
__device__ __align__(16) int   g_bsum [256];
__device__ __align__(16) int   g_boff [256];
// weight fragments: [kstep][ntile][lane] uint4 {b0hi,b1hi,b0lo,b1lo}
__device__ __align__(16) uint4 g_bf1 [8  * 16 * 32];   // layer1 (K2=128):  64KB
__device__ __align__(16) uint4 g_bf2 [16 * 16 * 32];   // layer2 (K2=256): 128KB

// ---------------------------------------------------------------------------
__device__ __forceinline__ uint32_t smem_u32(const void* p) {
    uint32_t a;
    asm("{ .reg .u64 t; cvta.to.shared.u64 t, %1; cvt.u32.u64 %0, t; }"
        : "=r"(a) : "l"(p));
    return a;
}
__device__ __forceinline__ uint32_t bpack(float a, float b) {
    __nv_bfloat16 ha = __float2bfloat16_rn(a), hb = __float2bfloat16_rn(b);
    return (uint32_t)__bfloat16_as_ushort(ha)
         | ((uint32_t)__bfloat16_as_ushort(hb) << 16);
}

#define MMA_BF16(d, a, b0, b1)                                              \
    asm volatile("mma.sync.aligned.m16n8k16.row.col.f32.bf16.bf16.f32 "     \
        "{%0,%1,%2,%3}, {%4,%5,%6,%7}, {%8,%9}, {%0,%1,%2,%3};"             \
        : "+f"((d)[0]), "+f"((d)[1]), "+f"((d)[2]), "+f"((d)[3])            \
        : "r"((a)[0]), "r"((a)[1]), "r"((a)[2]), "r"((a)[3]),               \
          "r"(b0), "r"(b1))

#define LDMATRIX_X4(r, addr)                                                \
    asm volatile("ldmatrix.sync.aligned.m8n8.x4.shared.b16 "                \
        "{%0,%1,%2,%3}, [%4];"                                              \
        : "=r"((r)[0]), "=r"((r)[1]), "=r"((r)[2]), "=r"((r)[3])            \
        : "r"(addr))

// ---------------------------------------------------------------------------
// CSR build (unchanged from R11)
__global__ void hist_kernel(const int* __restrict__ ei, int E, int nnodes,
                            int* __restrict__ degi) {
    const int half2 = E >> 1;
    int i = blockIdx.x * blockDim.x + threadIdx.x;
    if (i < half2) {
        int2 d2 = __ldg(reinterpret_cast<const int2*>(ei + E) + i);
        if ((unsigned)d2.x < (unsigned)nnodes) atomicAdd(&degi[d2.x], 1);
        if ((unsigned)d2.y < (unsigned)nnodes) atomicAdd(&degi[d2.y], 1);
    }
    if ((E & 1) && i == 0) {
        int d = __ldg(&ei[E + E - 1]);
        if ((unsigned)d < (unsigned)nnodes) atomicAdd(&degi[d], 1);
    }
}

__global__ void scan_partial_kernel(const int* __restrict__ degi,
                                    int* __restrict__ bsum, int n) {
    __shared__ int s[SCAN_CHUNK];
    int t = threadIdx.x;
    int i = blockIdx.x * SCAN_CHUNK + t;
    s[t] = (i < n) ? degi[i] : 0;
    __syncthreads();
    for (int off = SCAN_CHUNK / 2; off > 0; off >>= 1) {
        if (t < off) s[t] += s[t + off];
        __syncthreads();
    }
    if (t == 0) bsum[blockIdx.x] = s[0];
}

__global__ void scan_bsum_kernel(const int* __restrict__ bsum,
                                 int* __restrict__ boff,
                                 int* __restrict__ rowp, int nblk, int n) {
    __shared__ int s[256];
    int t = threadIdx.x;
    s[t] = (t < nblk) ? bsum[t] : 0;
    __syncthreads();
    for (int off = 1; off < 256; off <<= 1) {
        int v = (t >= off) ? s[t - off] : 0;
        __syncthreads();
        s[t] += v;
        __syncthreads();
    }
    boff[t] = (t == 0) ? 0 : s[t - 1];
    if (t == 255) rowp[n] = s[255];
}

__global__ void scan_final_kernel(int* __restrict__ degi,
                                  const int* __restrict__ boff,
                                  int* __restrict__ rowp,
                                  int* __restrict__ curs,
                                  float* __restrict__ dinv, int n) {
    __shared__ int s[SCAN_CHUNK];
    int t = threadIdx.x;
    int i = blockIdx.x * SCAN_CHUNK + t;
    int d = (i < n) ? degi[i] : 0;
    s[t] = d;
    __syncthreads();
    for (int off = 1; off < SCAN_CHUNK; off <<= 1) {
        int v = (t >= off) ? s[t - off] : 0;
        __syncthreads();
        s[t] += v;
        __syncthreads();
    }
    if (i < n) {
        int excl = s[t] - d + boff[blockIdx.x];
        rowp[i] = excl;
        curs[i] = excl;
        dinv[i] = 1.0f / fmaxf((float)d, 1.0f);
        degi[i] = 0;
    }
}

__global__ void scatter_kernel(const int* __restrict__ ei, int E, int nnodes,
                               int* __restrict__ curs, int* __restrict__ csr) {
    const int half2 = E >> 1;
    int i = blockIdx.x * blockDim.x + threadIdx.x;
    if (i < half2) {
        int2 s2 = __ldg(reinterpret_cast<const int2*>(ei) + i);
        int2 d2 = __ldg(reinterpret_cast<const int2*>(ei + E) + i);
        if ((unsigned)s2.x < (unsigned)nnodes && (unsigned)d2.x < (unsigned)nnodes) {
            int pos = atomicAdd(&curs[d2.x], 1);
            csr[pos] = s2.x;
        }
        if ((unsigned)s2.y < (unsigned)nnodes && (unsigned)d2.y < (unsigned)nnodes) {
            int pos = atomicAdd(&curs[d2.y], 1);
            csr[pos] = s2.y;
        }
    }
    if ((E & 1) && i == 0) {
        int s = __ldg(&ei[E - 1]);
        int d = __ldg(&ei[E + E - 1]);
        if ((unsigned)s < (unsigned)nnodes && (unsigned)d < (unsigned)nnodes) {
            int pos = atomicAdd(&curs[d], 1);
            csr[pos] = s;
        }
    }
}

// Gather-reduce mean aggregation (unchanged).
template <int F4>
__global__ void gather_agg_kernel(const float4* __restrict__ in4,
                                  const int* __restrict__ rowp,
                                  const int* __restrict__ csr,
                                  const float* __restrict__ dinv,
                                  float4* __restrict__ aggout, int n) {
    constexpr int GPB = 256 / F4;
    const int node = blockIdx.x * GPB + (threadIdx.x / F4);
    const int lane = threadIdx.x & (F4 - 1);
    if (node >= n) return;

    const int beg = __ldg(&rowp[node]);
    const int end = __ldg(&rowp[node + 1]);

    float4 a0 = make_float4(0.f, 0.f, 0.f, 0.f);
    float4 a1 = make_float4(0.f, 0.f, 0.f, 0.f);
    float4 a2 = make_float4(0.f, 0.f, 0.f, 0.f);
    float4 a3 = make_float4(0.f, 0.f, 0.f, 0.f);

    int j = beg;
    for (; j + 4 <= end; j += 4) {
        int s0 = __ldg(&csr[j]);
        int s1 = __ldg(&csr[j + 1]);
        int s2 = __ldg(&csr[j + 2]);
        int s3 = __ldg(&csr[j + 3]);
        float4 v0 = __ldg(&in4[(size_t)s0 * F4 + lane]);
        float4 v1 = __ldg(&in4[(size_t)s1 * F4 + lane]);
        float4 v2 = __ldg(&in4[(size_t)s2 * F4 + lane]);
        float4 v3 = __ldg(&in4[(size_t)s3 * F4 + lane]);
        a0.x += v0.x; a0.y += v0.y; a0.z += v0.z; a0.w += v0.w;
        a1.x += v1.x; a1.y += v1.y; a1.z += v1.z; a1.w += v1.w;
        a2.x += v2.x; a2.y += v2.y; a2.z += v2.z; a2.w += v2.w;
        a3.x += v3.x; a3.y += v3.y; a3.z += v3.z; a3.w += v3.w;
    }
    for (; j < end; j++) {
        int s0 = __ldg(&csr[j]);
        float4 v0 = __ldg(&in4[(size_t)s0 * F4 + lane]);
        a0.x += v0.x; a0.y += v0.y; a0.z += v0.z; a0.w += v0.w;
    }

    const float di = __ldg(&dinv[node]);
    float4 r;
    r.x = (a0.x + a1.x + a2.x + a3.x) * di;
    r.y = (a0.y + a1.y + a2.y + a3.y) * di;
    r.z = (a0.z + a1.z + a2.z + a3.z) * di;
    r.w = (a0.w + a1.w + a2.w + a3.w) * di;
    aggout[(size_t)node * F4 + lane] = r;
}

// ---------------------------------------------------------------------------
// Pack weight fragments (both layers). B col-major [n][k]; frag per
// (kstep, ntile, lane): b0 = k{kb,kb+1}, b1 = k{kb+8,kb+9}, n = nt*8+lane/4,
// kb = kstep*16 + (lane%4)*2.  uint4 = {b0hi, b1hi, b0lo, b1lo}.
__global__ void pack_bfrag_kernel(const float* __restrict__ W1l,
                                  const float* __restrict__ W1r,
                                  const float* __restrict__ W2l,
                                  const float* __restrict__ W2r,
                                  uint4* __restrict__ bf1,
                                  uint4* __restrict__ bf2) {
    int i = blockIdx.x * blockDim.x + threadIdx.x;
    int lane = i & 31, nt = (i >> 5) & 15, ks = i >> 9;
    int nrow = nt * 8 + (lane >> 2);
    int kb = (ks & 15) * 16 + (lane & 3) * 2;

    if (i < 8 * 16 * 32) {   // layer1, K=64
        float v[4], hi[4], lo[4];
#pragma unroll
        for (int q = 0; q < 4; q++) {
            int k = kb + (q & 1) + (q >> 1) * 8;
            v[q] = (k < F_IN) ? W1l[nrow * F_IN + k]
                              : W1r[nrow * F_IN + (k - F_IN)];
            hi[q] = __bfloat162float(__float2bfloat16_rn(v[q]));
            lo[q] = v[q] - hi[q];
        }
        uint4 r;
        r.x = bpack(hi[0], hi[1]); r.y = bpack(hi[2], hi[3]);
        r.z = bpack(lo[0], lo[1]); r.w = bpack(lo[2], lo[3]);
        bf1[i] = r;
    }
    if (i < 16 * 16 * 32) {  // layer2, K=128
        float v[4], hi[4], lo[4];
#pragma unroll
        for (int q = 0; q < 4; q++) {
            int k = kb + (q & 1) + (q >> 1) * 8;
            v[q] = (k < F_H) ? W2l[nrow * F_H + k]
                             : W2r[nrow * F_H + (k - F_H)];
            hi[q] = __bfloat162float(__float2bfloat16_rn(v[q]));
            lo[q] = v[q] - hi[q];
        }
        uint4 r;
        r.x = bpack(hi[0], hi[1]); r.y = bpack(hi[2], hi[3]);
        r.z = bpack(lo[0], lo[1]); r.w = bpack(lo[2], lo[3]);
        bf2[i] = r;
    }
}

// ---------------------------------------------------------------------------
// Dense layer via mma.sync bf16 split.
// CTA: 256 thr (8 warps), tile 128 nodes x 128 outs. Warp w: rows w*16..+15.
// K2 = 2*SRC_K total k (agg || x), staged in 64-k chunks as bf16 hi/lo.
template <int K2, bool RELU>
__global__ void __launch_bounds__(256)
dense_mma_kernel(const float* __restrict__ xin,
                 const float* __restrict__ agg,
                 const uint4* __restrict__ bfrag,
                 const float* __restrict__ bias,
                 float* __restrict__ out, int n) {
    constexpr int NCH = K2 / 64;     // 64-k chunks
    extern __shared__ char smem[];
    char*  smA   = smem;                                   // hi @0, lo @A_TILE
    float* sBias = reinterpret_cast<float*>(smem + SMEM_BIAS_OFF);
    const uint32_t sA_u32 = smem_u32(smem);

    const int tid  = threadIdx.x;
    const int wid  = tid >> 5;
    const int lane = tid & 31;
    const int base = blockIdx.x * 128;

    if (tid < 128) sBias[tid] = bias[tid];

    float d[16][4];
#pragma unroll
    for (int nt = 0; nt < 16; nt++) {
        d[nt][0] = 0.f; d[nt][1] = 0.f; d[nt][2] = 0.f; d[nt][3] = 0.f;
    }

#pragma unroll
    for (int c = 0; c < NCH; c++) {
        // ---- stage A chunk: 128 rows x 64 k, fp32 -> bf16 hi/lo ----
        {
            const float* src = (c < NCH / 2) ? (agg + c * 64)
                                             : (xin + (c - NCH / 2) * 64);
            const float2* s2 = reinterpret_cast<const float2*>(src);
            for (int i = tid; i < 128 * 32; i += 256) {
                int r  = i >> 5;
                int kp = i & 31;
                float2 v = make_float2(0.f, 0.f);
                int node = base + r;
                if (node < n) v = s2[(size_t)node * (K2 / 4) + kp];
                float hx = __bfloat162float(__float2bfloat16_rn(v.x));
                float hy = __bfloat162float(__float2bfloat16_rn(v.y));
                uint32_t hw = bpack(hx, hy);
                uint32_t lw = bpack(v.x - hx, v.y - hy);
                *reinterpret_cast<uint32_t*>(smA + r * A_STRIDE + kp * 4) = hw;
                *reinterpret_cast<uint32_t*>(smA + A_TILE + r * A_STRIDE + kp * 4) = lw;
            }
        }
        __syncthreads();

        // ---- 4 k-steps of 16 ----
#pragma unroll
        for (int ks = 0; ks < 4; ks++) {
            const int gk = c * 4 + ks;
            uint32_t ah[4], al[4];
            {
                int row = lane & 15;
                int hf  = lane >> 4;
                uint32_t off = (uint32_t)((wid * 16 + row) * A_STRIDE
                                          + ks * 32 + hf * 16);
                LDMATRIX_X4(ah, sA_u32 + off);
                LDMATRIX_X4(al, sA_u32 + A_TILE + off);
            }
#pragma unroll
            for (int nt = 0; nt < 16; nt++) {
                uint4 bf = __ldg(&bfrag[(size_t)(gk * 16 + nt) * 32 + lane]);
                MMA_BF16(d[nt], ah, bf.x, bf.y);   // hi * hi
                MMA_BF16(d[nt], ah, bf.z, bf.w);   // hi * lo
                MMA_BF16(d[nt], al, bf.x, bf.y);   // lo * hi
            }
        }
        __syncthreads();
    }

    // ---- epilogue: bias + relu, float2 stores ----
    const int r0 = base + wid * 16 + (lane >> 2);
    const int r1 = r0 + 8;
    const int cb = (lane & 3) * 2;
    float2* o2 = reinterpret_cast<float2*>(out);
#pragma unroll
    for (int nt = 0; nt < 16; nt++) {
        int col = nt * 8 + cb;
        float bx = sBias[col], by = sBias[col + 1];
        if (r0 < n) {
            float2 o = make_float2(d[nt][0] + bx, d[nt][1] + by);
            if (RELU) { o.x = fmaxf(o.x, 0.f); o.y = fmaxf(o.y, 0.f); }
            o2[(size_t)r0 * 64 + (col >> 1)] = o;
        }
        if (r1 < n) {
            float2 o = make_float2(d[nt][2] + bx, d[nt][3] + by);
            if (RELU) { o.x = fmaxf(o.x, 0.f); o.y = fmaxf(o.y, 0.f); }
            o2[(size_t)r1 * 64 + (col >> 1)] = o;
        }
    }
}

// ---------------------------------------------------------------------------
extern "C" void kernel_launch(void* const* d_in, const int* in_sizes, int n_in,
                              void* d_out, int out_size) {
    const float* x    = (const float*)d_in[0];
    const int*   ei   = (const int*)d_in[1];
    const float* W1_l = (const float*)d_in[2];
    const float* b1   = (const float*)d_in[3];
    const float* W1_r = (const float*)d_in[4];
    const float* W2_l = (const float*)d_in[5];
    const float* b2   = (const float*)d_in[6];
    const float* W2_r = (const float*)d_in[7];
    float*       out  = (float*)d_out;

    const int n = in_sizes[0] / F_IN;   // 100000
    const int E = in_sizes[1] / 2;      // 1600000
    const int nblk = (n + SCAN_CHUNK - 1) / SCAN_CHUNK;

    void *p_agg1, *p_h, *p_agg2, *p_dinv, *p_degi, *p_rowp, *p_curs, *p_csr,
         *p_bsum, *p_boff, *p_bf1, *p_bf2;
    cudaGetSymbolAddress(&p_agg1, g_agg1);
    cudaGetSymbolAddress(&p_h,    g_h);
    cudaGetSymbolAddress(&p_agg2, g_agg2);
    cudaGetSymbolAddress(&p_dinv, g_dinv);
    cudaGetSymbolAddress(&p_degi, g_degi);
    cudaGetSymbolAddress(&p_rowp, g_rowp);
    cudaGetSymbolAddress(&p_curs, g_curs);
    cudaGetSymbolAddress(&p_csr,  g_csr);
    cudaGetSymbolAddress(&p_bsum, g_bsum);
    cudaGetSymbolAddress(&p_boff, g_boff);
    cudaGetSymbolAddress(&p_bf1,  g_bf1);
    cudaGetSymbolAddress(&p_bf2,  g_bf2);
    float* agg1 = (float*)p_agg1;
    float* h    = (float*)p_h;
    float* agg2 = (float*)p_agg2;
    float* dinv = (float*)p_dinv;
    int*   degi = (int*)p_degi;
    int*   rowp = (int*)p_rowp;
    int*   curs = (int*)p_curs;
    int*   csr  = (int*)p_csr;
    int*   bsum = (int*)p_bsum;
    int*   boff = (int*)p_boff;
    uint4* bf1  = (uint4*)p_bf1;
    uint4* bf2  = (uint4*)p_bf2;

    cudaFuncSetAttribute(dense_mma_kernel<128, true>,
                         cudaFuncAttributeMaxDynamicSharedMemorySize, SMEM_TOTAL_D);
    cudaFuncSetAttribute(dense_mma_kernel<256, false>,
                         cudaFuncAttributeMaxDynamicSharedMemorySize, SMEM_TOTAL_D);

    // CSR build
    hist_kernel<<<((E >> 1) + 255) / 256, 256>>>(ei, E, n, degi);
    scan_partial_kernel<<<nblk, SCAN_CHUNK>>>(degi, bsum, n);
    scan_bsum_kernel<<<1, 256>>>(bsum, boff, rowp, nblk, n);
    scan_final_kernel<<<nblk, SCAN_CHUNK>>>(degi, boff, rowp, curs, dinv, n);
    scatter_kernel<<<((E >> 1) + 255) / 256, 256>>>(ei, E, n, curs, csr);

    // weight fragments (both layers), once
    pack_bfrag_kernel<<<(16 * 16 * 32 + 255) / 256, 256>>>(
        W1_l, W1_r, W2_l, W2_r, bf1, bf2);

    const int dblk = (n + 127) / 128;

    // layer 1
    gather_agg_kernel<F_IN / 4><<<(n * (F_IN / 4) + 255) / 256, 256>>>(
        (const float4*)x, rowp, csr, dinv, (float4*)agg1, n);
    dense_mma_kernel<128, true><<<dblk, 256, SMEM_TOTAL_D>>>(
        x, agg1, bf1, b1, h, n);

    // layer 2
    gather_agg_kernel<F_H / 4><<<(n * (F_H / 4) + 255) / 256, 256>>>(
        (const float4*)h, rowp, csr, dinv, (float4*)agg2, n);
    dense_mma_kernel<256, false><<<dblk, 256, SMEM_TOTAL_D>>>(
        h, agg2, bf2, b2, out, n);
}

// round 14
// speedup vs baseline: 1.9852x; 1.0603x over previous
#include <cuda_runtime.h>
#include <cuda_bf16.h>
#include <cstdint>

// ---------------------------------------------------------------------------
// GraphSAGE 2-layer backbone.
// R14: dense mma.sync bf16-split kernel gets DOUBLE-BUFFERED A staging:
//      stage(c+1) overlaps MMA(c); one __syncthreads per chunk (was two).
// CSR gather-reduce aggregation unchanged.
// ---------------------------------------------------------------------------

static constexpr int NN   = 100000;
static constexpr int EE   = 1600000;
static constexpr int F_IN = 64;
static constexpr int F_H  = 128;
static constexpr int SCAN_CHUNK = 512;

// A-tile smem: 128 rows, 64 k bf16 per chunk, row stride 144B.
static constexpr int A_STRIDE = 144;
static constexpr int A_TILE   = 128 * A_STRIDE;            // 18432 B per split
static constexpr int A_BUF    = 2 * A_TILE;                 // hi + lo
static constexpr int SMEM_BIAS_OFF = 2 * A_BUF;             // 73728
static constexpr int SMEM_TOTAL_D  = SMEM_BIAS_OFF + 512;   // 74240

// scratch
__device__ __align__(16) float g_agg1 [(size_t)NN * F_IN];
__device__ __align__(16) float g_h    [(size_t)NN * F_H];
__device__ __align__(16) float g_agg2 [(size_t)NN * F_H];
__device__ __align__(16) float g_dinv [NN];
__device__ __align__(16) int   g_degi [NN];
__device__ __align__(16) int   g_rowp [NN + 1];
__device__ __align__(16) int   g_curs [NN];
__device__ __align__(16) int   g_csr  [EE];
__device__ __align__(16) int   g_bsum [256];
__device__ __align__(16) int   g_boff [256];
// weight fragments: [kstep][ntile][lane] uint4 {b0hi,b1hi,b0lo,b1lo}
__device__ __align__(16) uint4 g_bf1 [8  * 16 * 32];
__device__ __align__(16) uint4 g_bf2 [16 * 16 * 32];

// ---------------------------------------------------------------------------
__device__ __forceinline__ uint32_t smem_u32(const void* p) {
    uint32_t a;
    asm("{ .reg .u64 t; cvta.to.shared.u64 t, %1; cvt.u32.u64 %0, t; }"
        : "=r"(a) : "l"(p));
    return a;
}
__device__ __forceinline__ uint32_t bpack(float a, float b) {
    __nv_bfloat16 ha = __float2bfloat16_rn(a), hb = __float2bfloat16_rn(b);
    return (uint32_t)__bfloat16_as_ushort(ha)
         | ((uint32_t)__bfloat16_as_ushort(hb) << 16);
}

#define MMA_BF16(d, a, b0, b1)                                              \
    asm volatile("mma.sync.aligned.m16n8k16.row.col.f32.bf16.bf16.f32 "     \
        "{%0,%1,%2,%3}, {%4,%5,%6,%7}, {%8,%9}, {%0,%1,%2,%3};"             \
        : "+f"((d)[0]), "+f"((d)[1]), "+f"((d)[2]), "+f"((d)[3])            \
        : "r"((a)[0]), "r"((a)[1]), "r"((a)[2]), "r"((a)[3]),               \
          "r"(b0), "r"(b1))

#define LDMATRIX_X4(r, addr)                                                \
    asm volatile("ldmatrix.sync.aligned.m8n8.x4.shared.b16 "                \
        "{%0,%1,%2,%3}, [%4];"                                              \
        : "=r"((r)[0]), "=r"((r)[1]), "=r"((r)[2]), "=r"((r)[3])            \
        : "r"(addr))

// ---------------------------------------------------------------------------
// CSR build (unchanged)
__global__ void hist_kernel(const int* __restrict__ ei, int E, int nnodes,
                            int* __restrict__ degi) {
    const int half2 = E >> 1;
    int i = blockIdx.x * blockDim.x + threadIdx.x;
    if (i < half2) {
        int2 d2 = __ldg(reinterpret_cast<const int2*>(ei + E) + i);
        if ((unsigned)d2.x < (unsigned)nnodes) atomicAdd(&degi[d2.x], 1);
        if ((unsigned)d2.y < (unsigned)nnodes) atomicAdd(&degi[d2.y], 1);
    }
    if ((E & 1) && i == 0) {
        int d = __ldg(&ei[E + E - 1]);
        if ((unsigned)d < (unsigned)nnodes) atomicAdd(&degi[d], 1);
    }
}

__global__ void scan_partial_kernel(const int* __restrict__ degi,
                                    int* __restrict__ bsum, int n) {
    __shared__ int s[SCAN_CHUNK];
    int t = threadIdx.x;
    int i = blockIdx.x * SCAN_CHUNK + t;
    s[t] = (i < n) ? degi[i] : 0;
    __syncthreads();
    for (int off = SCAN_CHUNK / 2; off > 0; off >>= 1) {
        if (t < off) s[t] += s[t + off];
        __syncthreads();
    }
    if (t == 0) bsum[blockIdx.x] = s[0];
}

__global__ void scan_bsum_kernel(const int* __restrict__ bsum,
                                 int* __restrict__ boff,
                                 int* __restrict__ rowp, int nblk, int n) {
    __shared__ int s[256];
    int t = threadIdx.x;
    s[t] = (t < nblk) ? bsum[t] : 0;
    __syncthreads();
    for (int off = 1; off < 256; off <<= 1) {
        int v = (t >= off) ? s[t - off] : 0;
        __syncthreads();
        s[t] += v;
        __syncthreads();
    }
    boff[t] = (t == 0) ? 0 : s[t - 1];
    if (t == 255) rowp[n] = s[255];
}

__global__ void scan_final_kernel(int* __restrict__ degi,
                                  const int* __restrict__ boff,
                                  int* __restrict__ rowp,
                                  int* __restrict__ curs,
                                  float* __restrict__ dinv, int n) {
    __shared__ int s[SCAN_CHUNK];
    int t = threadIdx.x;
    int i = blockIdx.x * SCAN_CHUNK + t;
    int d = (i < n) ? degi[i] : 0;
    s[t] = d;
    __syncthreads();
    for (int off = 1; off < SCAN_CHUNK; off <<= 1) {
        int v = (t >= off) ? s[t - off] : 0;
        __syncthreads();
        s[t] += v;
        __syncthreads();
    }
    if (i < n) {
        int excl = s[t] - d + boff[blockIdx.x];
        rowp[i] = excl;
        curs[i] = excl;
        dinv[i] = 1.0f / fmaxf((float)d, 1.0f);
        degi[i] = 0;
    }
}

__global__ void scatter_kernel(const int* __restrict__ ei, int E, int nnodes,
                               int* __restrict__ curs, int* __restrict__ csr) {
    const int half2 = E >> 1;
    int i = blockIdx.x * blockDim.x + threadIdx.x;
    if (i < half2) {
        int2 s2 = __ldg(reinterpret_cast<const int2*>(ei) + i);
        int2 d2 = __ldg(reinterpret_cast<const int2*>(ei + E) + i);
        if ((unsigned)s2.x < (unsigned)nnodes && (unsigned)d2.x < (unsigned)nnodes) {
            int pos = atomicAdd(&curs[d2.x], 1);
            csr[pos] = s2.x;
        }
        if ((unsigned)s2.y < (unsigned)nnodes && (unsigned)d2.y < (unsigned)nnodes) {
            int pos = atomicAdd(&curs[d2.y], 1);
            csr[pos] = s2.y;
        }
    }
    if ((E & 1) && i == 0) {
        int s = __ldg(&ei[E - 1]);
        int d = __ldg(&ei[E + E - 1]);
        if ((unsigned)s < (unsigned)nnodes && (unsigned)d < (unsigned)nnodes) {
            int pos = atomicAdd(&curs[d], 1);
            csr[pos] = s;
        }
    }
}

// Gather-reduce mean aggregation (unchanged).
template <int F4>
__global__ void gather_agg_kernel(const float4* __restrict__ in4,
                                  const int* __restrict__ rowp,
                                  const int* __restrict__ csr,
                                  const float* __restrict__ dinv,
                                  float4* __restrict__ aggout, int n) {
    constexpr int GPB = 256 / F4;
    const int node = blockIdx.x * GPB + (threadIdx.x / F4);
    const int lane = threadIdx.x & (F4 - 1);
    if (node >= n) return;

    const int beg = __ldg(&rowp[node]);
    const int end = __ldg(&rowp[node + 1]);

    float4 a0 = make_float4(0.f, 0.f, 0.f, 0.f);
    float4 a1 = make_float4(0.f, 0.f, 0.f, 0.f);
    float4 a2 = make_float4(0.f, 0.f, 0.f, 0.f);
    float4 a3 = make_float4(0.f, 0.f, 0.f, 0.f);

    int j = beg;
    for (; j + 4 <= end; j += 4) {
        int s0 = __ldg(&csr[j]);
        int s1 = __ldg(&csr[j + 1]);
        int s2 = __ldg(&csr[j + 2]);
        int s3 = __ldg(&csr[j + 3]);
        float4 v0 = __ldg(&in4[(size_t)s0 * F4 + lane]);
        float4 v1 = __ldg(&in4[(size_t)s1 * F4 + lane]);
        float4 v2 = __ldg(&in4[(size_t)s2 * F4 + lane]);
        float4 v3 = __ldg(&in4[(size_t)s3 * F4 + lane]);
        a0.x += v0.x; a0.y += v0.y; a0.z += v0.z; a0.w += v0.w;
        a1.x += v1.x; a1.y += v1.y; a1.z += v1.z; a1.w += v1.w;
        a2.x += v2.x; a2.y += v2.y; a2.z += v2.z; a2.w += v2.w;
        a3.x += v3.x; a3.y += v3.y; a3.z += v3.z; a3.w += v3.w;
    }
    for (; j < end; j++) {
        int s0 = __ldg(&csr[j]);
        float4 v0 = __ldg(&in4[(size_t)s0 * F4 + lane]);
        a0.x += v0.x; a0.y += v0.y; a0.z += v0.z; a0.w += v0.w;
    }

    const float di = __ldg(&dinv[node]);
    float4 r;
    r.x = (a0.x + a1.x + a2.x + a3.x) * di;
    r.y = (a0.y + a1.y + a2.y + a3.y) * di;
    r.z = (a0.z + a1.z + a2.z + a3.z) * di;
    r.w = (a0.w + a1.w + a2.w + a3.w) * di;
    aggout[(size_t)node * F4 + lane] = r;
}

// ---------------------------------------------------------------------------
// Pack weight fragments (unchanged from R13).
__global__ void pack_bfrag_kernel(const float* __restrict__ W1l,
                                  const float* __restrict__ W1r,
                                  const float* __restrict__ W2l,
                                  const float* __restrict__ W2r,
                                  uint4* __restrict__ bf1,
                                  uint4* __restrict__ bf2) {
    int i = blockIdx.x * blockDim.x + threadIdx.x;
    int lane = i & 31, nt = (i >> 5) & 15, ks = i >> 9;
    int nrow = nt * 8 + (lane >> 2);
    int kb = (ks & 15) * 16 + (lane & 3) * 2;

    if (i < 8 * 16 * 32) {
        float v[4], hi[4], lo[4];
#pragma unroll
        for (int q = 0; q < 4; q++) {
            int k = kb + (q & 1) + (q >> 1) * 8;
            v[q] = (k < F_IN) ? W1l[nrow * F_IN + k]
                              : W1r[nrow * F_IN + (k - F_IN)];
            hi[q] = __bfloat162float(__float2bfloat16_rn(v[q]));
            lo[q] = v[q] - hi[q];
        }
        uint4 r;
        r.x = bpack(hi[0], hi[1]); r.y = bpack(hi[2], hi[3]);
        r.z = bpack(lo[0], lo[1]); r.w = bpack(lo[2], lo[3]);
        bf1[i] = r;
    }
    if (i < 16 * 16 * 32) {
        float v[4], hi[4], lo[4];
#pragma unroll
        for (int q = 0; q < 4; q++) {
            int k = kb + (q & 1) + (q >> 1) * 8;
            v[q] = (k < F_H) ? W2l[nrow * F_H + k]
                             : W2r[nrow * F_H + (k - F_H)];
            hi[q] = __bfloat162float(__float2bfloat16_rn(v[q]));
            lo[q] = v[q] - hi[q];
        }
        uint4 r;
        r.x = bpack(hi[0], hi[1]); r.y = bpack(hi[2], hi[3]);
        r.z = bpack(lo[0], lo[1]); r.w = bpack(lo[2], lo[3]);
        bf2[i] = r;
    }
}

// ---------------------------------------------------------------------------
// Dense layer via mma.sync bf16 split, double-buffered A staging.
// Per chunk: stage(c+1) into the other buffer, then MMA(c), then ONE sync.
template <int K2, bool RELU>
__global__ void __launch_bounds__(256, 2)
dense_mma_kernel(const float* __restrict__ xin,
                 const float* __restrict__ agg,
                 const uint4* __restrict__ bfrag,
                 const float* __restrict__ bias,
                 float* __restrict__ out, int n) {
    constexpr int NCH = K2 / 64;
    extern __shared__ char smem[];
    float* sBias = reinterpret_cast<float*>(smem + SMEM_BIAS_OFF);
    const uint32_t sA_u32 = smem_u32(smem);

    const int tid  = threadIdx.x;
    const int wid  = tid >> 5;
    const int lane = tid & 31;
    const int base = blockIdx.x * 128;

    if (tid < 128) sBias[tid] = bias[tid];

    float d[16][4];
#pragma unroll
    for (int nt = 0; nt < 16; nt++) {
        d[nt][0] = 0.f; d[nt][1] = 0.f; d[nt][2] = 0.f; d[nt][3] = 0.f;
    }

    // staging: chunk c -> buffer (c&1). hi at +0, lo at +A_TILE.
    auto stage = [&](int c) {
        char* buf = smem + (c & 1) * A_BUF;
        const float* src = (c < NCH / 2) ? (agg + c * 64)
                                         : (xin + (c - NCH / 2) * 64);
        const float2* s2 = reinterpret_cast<const float2*>(src);
#pragma unroll
        for (int ii = 0; ii < 16; ii++) {
            int i  = tid + ii * 256;
            int r  = i >> 5;
            int kp = i & 31;
            float2 v = make_float2(0.f, 0.f);
            int node = base + r;
            if (node < n) v = s2[(size_t)node * (K2 / 4) + kp];
            float hx = __bfloat162float(__float2bfloat16_rn(v.x));
            float hy = __bfloat162float(__float2bfloat16_rn(v.y));
            *reinterpret_cast<uint32_t*>(buf + r * A_STRIDE + kp * 4)
                = bpack(hx, hy);
            *reinterpret_cast<uint32_t*>(buf + A_TILE + r * A_STRIDE + kp * 4)
                = bpack(v.x - hx, v.y - hy);
        }
    };

    stage(0);
    __syncthreads();

#pragma unroll
    for (int c = 0; c < NCH; c++) {
        if (c + 1 < NCH) stage(c + 1);          // overlaps MMA(c) cross-warp

        const uint32_t bufA = sA_u32 + (uint32_t)((c & 1) * A_BUF);
#pragma unroll
        for (int ks = 0; ks < 4; ks++) {
            const int gk = c * 4 + ks;
            uint32_t ah[4], al[4];
            {
                int row = lane & 15;
                int hf  = lane >> 4;
                uint32_t off = (uint32_t)((wid * 16 + row) * A_STRIDE
                                          + ks * 32 + hf * 16);
                LDMATRIX_X4(ah, bufA + off);
                LDMATRIX_X4(al, bufA + A_TILE + off);
            }
#pragma unroll
            for (int nt = 0; nt < 16; nt++) {
                uint4 bf = __ldg(&bfrag[(size_t)(gk * 16 + nt) * 32 + lane]);
                MMA_BF16(d[nt], ah, bf.x, bf.y);   // hi * hi
                MMA_BF16(d[nt], ah, bf.z, bf.w);   // hi * lo
                MMA_BF16(d[nt], al, bf.x, bf.y);   // lo * hi
            }
        }
        __syncthreads();    // buffers swap safely: one barrier per chunk
    }

    // epilogue: bias + relu, float2 stores
    const int r0 = base + wid * 16 + (lane >> 2);
    const int r1 = r0 + 8;
    const int cb = (lane & 3) * 2;
    float2* o2 = reinterpret_cast<float2*>(out);
#pragma unroll
    for (int nt = 0; nt < 16; nt++) {
        int col = nt * 8 + cb;
        float bx = sBias[col], by = sBias[col + 1];
        if (r0 < n) {
            float2 o = make_float2(d[nt][0] + bx, d[nt][1] + by);
            if (RELU) { o.x = fmaxf(o.x, 0.f); o.y = fmaxf(o.y, 0.f); }
            o2[(size_t)r0 * 64 + (col >> 1)] = o;
        }
        if (r1 < n) {
            float2 o = make_float2(d[nt][2] + bx, d[nt][3] + by);
            if (RELU) { o.x = fmaxf(o.x, 0.f); o.y = fmaxf(o.y, 0.f); }
            o2[(size_t)r1 * 64 + (col >> 1)] = o;
        }
    }
}

// ---------------------------------------------------------------------------
extern "C" void kernel_launch(void* const* d_in, const int* in_sizes, int n_in,
                              void* d_out, int out_size) {
    const float* x    = (const float*)d_in[0];
    const int*   ei   = (const int*)d_in[1];
    const float* W1_l = (const float*)d_in[2];
    const float* b1   = (const float*)d_in[3];
    const float* W1_r = (const float*)d_in[4];
    const float* W2_l = (const float*)d_in[5];
    const float* b2   = (const float*)d_in[6];
    const float* W2_r = (const float*)d_in[7];
    float*       out  = (float*)d_out;

    const int n = in_sizes[0] / F_IN;   // 100000
    const int E = in_sizes[1] / 2;      // 1600000
    const int nblk = (n + SCAN_CHUNK - 1) / SCAN_CHUNK;

    void *p_agg1, *p_h, *p_agg2, *p_dinv, *p_degi, *p_rowp, *p_curs, *p_csr,
         *p_bsum, *p_boff, *p_bf1, *p_bf2;
    cudaGetSymbolAddress(&p_agg1, g_agg1);
    cudaGetSymbolAddress(&p_h,    g_h);
    cudaGetSymbolAddress(&p_agg2, g_agg2);
    cudaGetSymbolAddress(&p_dinv, g_dinv);
    cudaGetSymbolAddress(&p_degi, g_degi);
    cudaGetSymbolAddress(&p_rowp, g_rowp);
    cudaGetSymbolAddress(&p_curs, g_curs);
    cudaGetSymbolAddress(&p_csr,  g_csr);
    cudaGetSymbolAddress(&p_bsum, g_bsum);
    cudaGetSymbolAddress(&p_boff, g_boff);
    cudaGetSymbolAddress(&p_bf1,  g_bf1);
    cudaGetSymbolAddress(&p_bf2,  g_bf2);
    float* agg1 = (float*)p_agg1;
    float* h    = (float*)p_h;
    float* agg2 = (float*)p_agg2;
    float* dinv = (float*)p_dinv;
    int*   degi = (int*)p_degi;
    int*   rowp = (int*)p_rowp;
    int*   curs = (int*)p_curs;
    int*   csr  = (int*)p_csr;
    int*   bsum = (int*)p_bsum;
    int*   boff = (int*)p_boff;
    uint4* bf1  = (uint4*)p_bf1;
    uint4* bf2  = (uint4*)p_bf2;

    cudaFuncSetAttribute(dense_mma_kernel<128, true>,
                         cudaFuncAttributeMaxDynamicSharedMemorySize, SMEM_TOTAL_D);
    cudaFuncSetAttribute(dense_mma_kernel<256, false>,
                         cudaFuncAttributeMaxDynamicSharedMemorySize, SMEM_TOTAL_D);

    // CSR build
    hist_kernel<<<((E >> 1) + 255) / 256, 256>>>(ei, E, n, degi);
    scan_partial_kernel<<<nblk, SCAN_CHUNK>>>(degi, bsum, n);
    scan_bsum_kernel<<<1, 256>>>(bsum, boff, rowp, nblk, n);
    scan_final_kernel<<<nblk, SCAN_CHUNK>>>(degi, boff, rowp, curs, dinv, n);
    scatter_kernel<<<((E >> 1) + 255) / 256, 256>>>(ei, E, n, curs, csr);

    // weight fragments
    pack_bfrag_kernel<<<(16 * 16 * 32 + 255) / 256, 256>>>(
        W1_l, W1_r, W2_l, W2_r, bf1, bf2);

    const int dblk = (n + 127) / 128;

    // layer 1
    gather_agg_kernel<F_IN / 4><<<(n * (F_IN / 4) + 255) / 256, 256>>>(
        (const float4*)x, rowp, csr, dinv, (float4*)agg1, n);
    dense_mma_kernel<128, true><<<dblk, 256, SMEM_TOTAL_D>>>(
        x, agg1, bf1, b1, h, n);

    // layer 2
    gather_agg_kernel<F_H / 4><<<(n * (F_H / 4) + 255) / 256, 256>>>(
        (const float4*)h, rowp, csr, dinv, (float4*)agg2, n);
    dense_mma_kernel<256, false><<<dblk, 256, SMEM_TOTAL_D>>>(
        h, agg2, bf2, b2, out, n);
}